// round 12
// baseline (speedup 1.0000x reference)
#include <cuda_runtime.h>
#include <cuda_bf16.h>
#include <cstdint>

#define MAX_N   (1 << 17)
#define NMODELS 8
#define H       128
#define TILE    128
#define NCTA    148
#define MLP_THREADS 256

// B row stride: 128 bf16 = 256B + 16B pad = 272B = 68 u32 (ldmatrix conflict-free)
#define BSTRIDE_U32 68
#define BUF_U32     (H * BSTRIDE_U32)      // 8704 u32 = 34816 B per image

// ---------------- scratch (device globals; no allocs allowed) ----------------
__device__ int    g_counts[NMODELS];       // atomic rank counters (self-reset in k_scan)
__device__ int    g_cnt[NMODELS];          // final per-model counts
__device__ int    g_tilebase[NMODELS + 1];
__device__ int    g_total_tiles;
__device__ int    g_perm[NMODELS * MAX_N]; // segmented
__device__ float4 g_xg[NMODELS * MAX_N];   // segmented normalized inputs
// transposed bf16 weight images B[n][k] ([layer*8+model][n][k-pairs])
__device__ __align__(16) uint32_t g_Bhi[16 * BUF_U32];
__device__ __align__(16) uint32_t g_Blo[16 * BUF_U32];
// packed layer0: per model, per col: (w0, w1, w2, b0)
__device__ __align__(16) float4   g_W0p[NMODELS * H];

// ---------------- helpers -----------------------------------------------------
__device__ __forceinline__ uint32_t smem_u32(const void* p) {
    uint32_t a;
    asm("{ .reg .u64 t; cvta.to.shared.u64 t, %1; cvt.u32.u64 %0, t; }"
        : "=r"(a) : "l"(p));
    return a;
}
__device__ __forceinline__ void mma16816(float* d, const uint32_t* a,
                                         uint32_t b0, uint32_t b1) {
    asm volatile(
        "mma.sync.aligned.m16n8k16.row.col.f32.bf16.bf16.f32 "
        "{%0,%1,%2,%3}, {%4,%5,%6,%7}, {%8,%9}, {%0,%1,%2,%3};"
        : "+f"(d[0]), "+f"(d[1]), "+f"(d[2]), "+f"(d[3])
        : "r"(a[0]), "r"(a[1]), "r"(a[2]), "r"(a[3]), "r"(b0), "r"(b1));
}
__device__ __forceinline__ void ldsm4(uint32_t* r, uint32_t addr) {
    asm volatile("ldmatrix.sync.aligned.m8n8.x4.shared.b16 {%0,%1,%2,%3}, [%4];"
                 : "=r"(r[0]), "=r"(r[1]), "=r"(r[2]), "=r"(r[3]) : "r"(addr));
}
// pack (v0 -> low half, v1 -> high half) as bf16x2; also return residuals
__device__ __forceinline__ uint32_t pack_hi_res(float v0, float v1,
                                                float& r0, float& r1) {
    __nv_bfloat162 h = {__float2bfloat16_rn(v0), __float2bfloat16_rn(v1)};
    r0 = v0 - __bfloat162float(h.x);
    r1 = v1 - __bfloat162float(h.y);
    uint32_t u;
    memcpy(&u, &h, 4);
    return u;
}
__device__ __forceinline__ uint32_t pack_bf16x2(float lo_val, float hi_val) {
    uint32_t r;   // %1 -> upper half, %2 -> lower half
    asm("cvt.rn.bf16x2.f32 %0, %1, %2;" : "=r"(r) : "f"(hi_val), "f"(lo_val));
    return r;
}

// ---------------- model index (bit-exact vs reference) ------------------------
__device__ __forceinline__ int model_index(float x0, float x1, float x2) {
    const float den = 2.0f + 1e-6f;
    int c0 = (int)((x2 + 1.0f) / den * 2.0f);
    int c1 = (int)((x1 + 1.0f) / den * 2.0f);
    int c2 = (int)((x0 + 1.0f) / den * 2.0f);
    return c0 + 2 * c1 + 4 * c2;
}

// ---------------- pass 1: fused classify+scatter (+weight prep blocks) -------
__global__ void k_scatter_prep(const float* __restrict__ x,
                               const float* __restrict__ mins,
                               const float* __restrict__ maxs, int n, int SB,
                               const float* __restrict__ W0,
                               const float* __restrict__ b0,
                               const float* __restrict__ W1,
                               const float* __restrict__ W2) {
    const int blk = blockIdx.x;
    const int tid = threadIdx.x;
    if (blk < SB) {
        __shared__ int sh_cnt[NMODELS];
        __shared__ int sh_base[NMODELS];
        if (tid < NMODELS) sh_cnt[tid] = 0;
        __syncthreads();
        int i = blk * blockDim.x + tid;
        int m = 0, rank = 0;
        float x0 = 0.f, x1 = 0.f, x2 = 0.f;
        if (i < n) {
            x0 = x[3 * i]; x1 = x[3 * i + 1]; x2 = x[3 * i + 2];
            m = model_index(x0, x1, x2);
            rank = atomicAdd(&sh_cnt[m], 1);
        }
        __syncthreads();
        if (tid < NMODELS)
            sh_base[tid] = sh_cnt[tid] ? atomicAdd(&g_counts[tid], sh_cnt[tid]) : 0;
        __syncthreads();
        if (i < n) {
            int pos = m * MAX_N + sh_base[m] + rank;
            g_perm[pos] = i;
            float mn0 = mins[3 * m], mn1 = mins[3 * m + 1], mn2 = mins[3 * m + 2];
            float mx0 = maxs[3 * m], mx1 = maxs[3 * m + 1], mx2 = maxs[3 * m + 2];
            g_xg[pos] = make_float4(-1.0f + 2.0f * (x0 - mn0) / (mx0 - mn0),
                                    -1.0f + 2.0f * (x1 - mn1) / (mx1 - mn1),
                                    -1.0f + 2.0f * (x2 - mn2) / (mx2 - mn2), 0.0f);
        }
    } else if (blk < SB + 512) {
        int t = (blk - SB) * 256 + tid;        // 0 .. 131071
        int lm = t >> 13;                      // layer*8 + model
        int w  = t & 8191;
        int k2 = w >> 7;                       // pair of K columns
        int nn = w & 127;                      // consecutive -> coalesced loads
        const float* W = ((lm >> 3) ? W2 : W1) + (lm & 7) * H * H;
        int k = 2 * k2;
        float v0 = W[k * H + nn];              // B[n][k] = W[k][n]
        float v1 = W[(k + 1) * H + nn];
        float r0, r1;
        uint32_t hi = pack_hi_res(v0, v1, r0, r1);
        uint32_t lo = pack_bf16x2(r0, r1);
        int off = lm * BUF_U32 + nn * BSTRIDE_U32 + k2;
        g_Bhi[off] = hi;
        g_Blo[off] = lo;
    } else {
        for (int i = tid; i < NMODELS * H; i += 256) {
            int m = i >> 7, c = i & 127;
            g_W0p[i] = make_float4(W0[m * 384 + c], W0[m * 384 + 128 + c],
                                   W0[m * 384 + 256 + c], b0[m * H + c]);
        }
    }
}

// ---------------- pass 2: tiny scan -------------------------------------------
__global__ void k_scan() {
    if (threadIdx.x == 0) {
        int t = 0;
        for (int m = 0; m < NMODELS; m++) {
            int c = g_counts[m];
            g_counts[m] = 0;          // self-reset for graph replay
            g_cnt[m] = c;
            g_tilebase[m] = t;
            t += (c + TILE - 1) / TILE;
        }
        g_tilebase[NMODELS] = t;
        g_total_tiles = t;
    }
}

// ---------------- smem layout (bytes) -----------------------------------------
#define SB_B1HI 0
#define SB_B1LO (SB_B1HI + 34816)
#define SB_B2HI (SB_B1LO + 34816)
#define SB_B2LO (SB_B2HI + 34816)
#define SB_W0P  (SB_B2LO + 34816)          // 128 * float4 = 2048
#define SB_B1   (SB_W0P + 2048)            // 512
#define SB_B2   (SB_B1 + 512)
#define SB_W3   (SB_B2 + 512)
#define SMEM_TOTAL (SB_W3 + 512)

// one GEMM layer: acc[64] += split-bf16( A-frags ) @ B(smem images)
// two ntp tiles per step; MMAs rotate over 4 independent accumulators (dep dist 4)
__device__ __forceinline__ void mma_layer(float* acc,
                                          const uint32_t* a_hi,
                                          const uint32_t* a_lo,
                                          uint32_t bhi_base, uint32_t blo_base,
                                          uint32_t lane_off) {
    #pragma unroll
    for (int kt = 0; kt < 8; kt++) {
        #pragma unroll
        for (int np = 0; np < 4; np++) {
            const int ntp0 = 2 * np, ntp1 = 2 * np + 1;
            uint32_t bh0[4], bl0[4], bh1[4], bl1[4];
            const uint32_t off0 = (uint32_t)(ntp0 * 16 * 272 + kt * 32) + lane_off;
            const uint32_t off1 = (uint32_t)(ntp1 * 16 * 272 + kt * 32) + lane_off;
            ldsm4(bh0, bhi_base + off0);
            ldsm4(bh1, bhi_base + off1);
            ldsm4(bl0, blo_base + off0);
            ldsm4(bl1, blo_base + off1);
            float* d0 = acc + (16 * np);
            float* d1 = acc + (16 * np + 4);
            float* d2 = acc + (16 * np + 8);
            float* d3 = acc + (16 * np + 12);
            const uint32_t* ah = a_hi + kt * 4;
            const uint32_t* al = a_lo + kt * 4;
            mma16816(d0, ah, bh0[0], bh0[1]);
            mma16816(d1, ah, bh0[2], bh0[3]);
            mma16816(d2, ah, bh1[0], bh1[1]);
            mma16816(d3, ah, bh1[2], bh1[3]);
            mma16816(d0, al, bh0[0], bh0[1]);
            mma16816(d1, al, bh0[2], bh0[3]);
            mma16816(d2, al, bh1[0], bh1[1]);
            mma16816(d3, al, bh1[2], bh1[3]);
            mma16816(d0, ah, bl0[0], bl0[1]);
            mma16816(d1, ah, bl0[2], bl0[3]);
            mma16816(d2, ah, bl1[0], bl1[1]);
            mma16816(d3, ah, bl1[2], bl1[3]);
        }
    }
}

// ---------------- persistent fused-MLP kernel ---------------------------------
__global__ void __launch_bounds__(MLP_THREADS, 1)
k_mlp(const float* __restrict__ W3, const float* __restrict__ b1g,
      const float* __restrict__ b2g, const float* __restrict__ b3g,
      float* __restrict__ out) {
    extern __shared__ char smc[];
    const uint32_t sbase = smem_u32(smc);
    const int tid  = threadIdx.x;
    const int wid  = tid >> 5;
    const int lane = tid & 31;
    const int q2   = 2 * (lane & 3);
    const int grp  = lane >> 2;            // 0..7
    const int r0l  = wid * 16 + grp;       // local row A
    const int r1l  = r0l + 8;              // local row B

    // ldmatrix per-lane base offset within a B image
    const uint32_t lane_off =
        (uint32_t)(((lane & 7) + ((lane & 16) ? 8 : 0)) * 272 + ((lane & 8) ? 16 : 0));

    const int T = g_total_tiles;
    const int start = (int)((long long)blockIdx.x * T / NCTA);
    const int end   = (int)((long long)(blockIdx.x + 1) * T / NCTA);

    float4* W0ps = (float4*)(smc + SB_W0P);
    float*  b1s  = (float*)(smc + SB_B1);
    float*  b2s  = (float*)(smc + SB_B2);
    float*  w3s  = (float*)(smc + SB_W3);

    int cur_m = -1;
    float b3v = 0.0f;

    for (int t = start; t < end; t++) {
        int m = 0;
        while (m < NMODELS - 1 && t >= g_tilebase[m + 1]) m++;

        if (m != cur_m) {
            __syncthreads();               // prior tile's ldmatrix readers done
            const uint4* s1h = (const uint4*)(g_Bhi + (0 * 8 + m) * BUF_U32);
            const uint4* s1l = (const uint4*)(g_Blo + (0 * 8 + m) * BUF_U32);
            const uint4* s2h = (const uint4*)(g_Bhi + (1 * 8 + m) * BUF_U32);
            const uint4* s2l = (const uint4*)(g_Blo + (1 * 8 + m) * BUF_U32);
            uint4* d1h = (uint4*)(smc + SB_B1HI);
            uint4* d1l = (uint4*)(smc + SB_B1LO);
            uint4* d2h = (uint4*)(smc + SB_B2HI);
            uint4* d2l = (uint4*)(smc + SB_B2LO);
            for (int i = tid; i < 2176; i += MLP_THREADS) {
                d1h[i] = s1h[i];
                d1l[i] = s1l[i];
                d2h[i] = s2h[i];
                d2l[i] = s2l[i];
            }
            if (tid < H) {
                W0ps[tid] = g_W0p[m * H + tid];
                b1s[tid]  = b1g[m * H + tid];
                b2s[tid]  = b2g[m * H + tid];
                w3s[tid]  = W3[m * H + tid];
            }
            b3v = b3g[m];
            cur_m = m;
            __syncthreads();
        }

        const int row0 = (t - g_tilebase[m]) * TILE;      // within segment
        const int rows = min(TILE, g_cnt[m] - row0);
        const int seg  = m * MAX_N + row0;

        // ---- layer 0: compute A-fragments directly in registers -------------
        float4 xa = (r0l < rows) ? g_xg[seg + r0l] : make_float4(0.f, 0.f, 0.f, 0.f);
        float4 xb = (r1l < rows) ? g_xg[seg + r1l] : make_float4(0.f, 0.f, 0.f, 0.f);

        uint32_t a_hi[32], a_lo[32];
        #pragma unroll
        for (int kt = 0; kt < 8; kt++) {
            int c0 = kt * 16 + q2;
            float4 wA0 = W0ps[c0], wA1 = W0ps[c0 + 1];
            float4 wB0 = W0ps[c0 + 8], wB1 = W0ps[c0 + 9];
            float va0 = fmaxf(fmaf(xa.x, wA0.x, fmaf(xa.y, wA0.y, fmaf(xa.z, wA0.z, wA0.w))), 0.f);
            float va1 = fmaxf(fmaf(xa.x, wA1.x, fmaf(xa.y, wA1.y, fmaf(xa.z, wA1.z, wA1.w))), 0.f);
            float vb0 = fmaxf(fmaf(xb.x, wA0.x, fmaf(xb.y, wA0.y, fmaf(xb.z, wA0.z, wA0.w))), 0.f);
            float vb1 = fmaxf(fmaf(xb.x, wA1.x, fmaf(xb.y, wA1.y, fmaf(xb.z, wA1.z, wA1.w))), 0.f);
            float va2 = fmaxf(fmaf(xa.x, wB0.x, fmaf(xa.y, wB0.y, fmaf(xa.z, wB0.z, wB0.w))), 0.f);
            float va3 = fmaxf(fmaf(xa.x, wB1.x, fmaf(xa.y, wB1.y, fmaf(xa.z, wB1.z, wB1.w))), 0.f);
            float vb2 = fmaxf(fmaf(xb.x, wB0.x, fmaf(xb.y, wB0.y, fmaf(xb.z, wB0.z, wB0.w))), 0.f);
            float vb3 = fmaxf(fmaf(xb.x, wB1.x, fmaf(xb.y, wB1.y, fmaf(xb.z, wB1.z, wB1.w))), 0.f);
            float ra0, ra1, rb0, rb1, ra2, ra3, rb2, rb3;
            a_hi[kt * 4 + 0] = pack_hi_res(va0, va1, ra0, ra1);
            a_hi[kt * 4 + 1] = pack_hi_res(vb0, vb1, rb0, rb1);
            a_hi[kt * 4 + 2] = pack_hi_res(va2, va3, ra2, ra3);
            a_hi[kt * 4 + 3] = pack_hi_res(vb2, vb3, rb2, rb3);
            a_lo[kt * 4 + 0] = pack_bf16x2(ra0, ra1);
            a_lo[kt * 4 + 1] = pack_bf16x2(rb0, rb1);
            a_lo[kt * 4 + 2] = pack_bf16x2(ra2, ra3);
            a_lo[kt * 4 + 3] = pack_bf16x2(rb2, rb3);
        }

        // ---- layer 1 ---------------------------------------------------------
        float acc[64];
        #pragma unroll
        for (int i = 0; i < 64; i++) acc[i] = 0.0f;
        mma_layer(acc, a_hi, a_lo, sbase + SB_B1HI, sbase + SB_B1LO, lane_off);

        // epilogue: bias + relu -> new A-fragments (C frag layout == A frag layout)
        #pragma unroll
        for (int kt = 0; kt < 8; kt++) {
            int ntA = 2 * kt, ntB = 2 * kt + 1;
            int cbA = ntA * 8 + q2, cbB = ntB * 8 + q2;
            float bA0 = b1s[cbA], bA1 = b1s[cbA + 1];
            float bB0 = b1s[cbB], bB1 = b1s[cbB + 1];
            float va0 = fmaxf(acc[ntA * 4 + 0] + bA0, 0.f);
            float va1 = fmaxf(acc[ntA * 4 + 1] + bA1, 0.f);
            float vb0 = fmaxf(acc[ntA * 4 + 2] + bA0, 0.f);
            float vb1 = fmaxf(acc[ntA * 4 + 3] + bA1, 0.f);
            float va2 = fmaxf(acc[ntB * 4 + 0] + bB0, 0.f);
            float va3 = fmaxf(acc[ntB * 4 + 1] + bB1, 0.f);
            float vb2 = fmaxf(acc[ntB * 4 + 2] + bB0, 0.f);
            float vb3 = fmaxf(acc[ntB * 4 + 3] + bB1, 0.f);
            float ra0, ra1, rb0, rb1, ra2, ra3, rb2, rb3;
            a_hi[kt * 4 + 0] = pack_hi_res(va0, va1, ra0, ra1);
            a_hi[kt * 4 + 1] = pack_hi_res(vb0, vb1, rb0, rb1);
            a_hi[kt * 4 + 2] = pack_hi_res(va2, va3, ra2, ra3);
            a_hi[kt * 4 + 3] = pack_hi_res(vb2, vb3, rb2, rb3);
            a_lo[kt * 4 + 0] = pack_bf16x2(ra0, ra1);
            a_lo[kt * 4 + 1] = pack_bf16x2(rb0, rb1);
            a_lo[kt * 4 + 2] = pack_bf16x2(ra2, ra3);
            a_lo[kt * 4 + 3] = pack_bf16x2(rb2, rb3);
        }

        // ---- layer 2 ---------------------------------------------------------
        #pragma unroll
        for (int i = 0; i < 64; i++) acc[i] = 0.0f;
        mma_layer(acc, a_hi, a_lo, sbase + SB_B2HI, sbase + SB_B2LO, lane_off);

        // ---- layer 3: relu + dot(w3) + cross-lane reduce ---------------------
        float s0 = 0.f, s1 = 0.f;
        #pragma unroll
        for (int nt = 0; nt < 16; nt++) {
            int cb = nt * 8 + q2;
            float w3a = w3s[cb], w3b = w3s[cb + 1];
            float b2a = b2s[cb], b2b = b2s[cb + 1];
            s0 = fmaf(fmaxf(acc[nt * 4 + 0] + b2a, 0.f), w3a, s0);
            s0 = fmaf(fmaxf(acc[nt * 4 + 1] + b2b, 0.f), w3b, s0);
            s1 = fmaf(fmaxf(acc[nt * 4 + 2] + b2a, 0.f), w3a, s1);
            s1 = fmaf(fmaxf(acc[nt * 4 + 3] + b2b, 0.f), w3b, s1);
        }
        s0 += __shfl_xor_sync(0xffffffffu, s0, 1);
        s0 += __shfl_xor_sync(0xffffffffu, s0, 2);
        s1 += __shfl_xor_sync(0xffffffffu, s1, 1);
        s1 += __shfl_xor_sync(0xffffffffu, s1, 2);
        if ((lane & 3) == 0) {
            if (r0l < rows) out[g_perm[seg + r0l]] = s0 + b3v;
            if (r1l < rows) out[g_perm[seg + r1l]] = s1 + b3v;
        }
    }
}

// ---------------- launch -------------------------------------------------------
extern "C" void kernel_launch(void* const* d_in, const int* in_sizes, int n_in,
                              void* d_out, int out_size) {
    const float* x    = (const float*)d_in[0];
    const float* W0   = (const float*)d_in[1];
    const float* b0   = (const float*)d_in[2];
    const float* W1   = (const float*)d_in[3];
    const float* b1   = (const float*)d_in[4];
    const float* W2   = (const float*)d_in[5];
    const float* b2   = (const float*)d_in[6];
    const float* W3   = (const float*)d_in[7];
    const float* b3   = (const float*)d_in[8];
    const float* mins = (const float*)d_in[9];
    const float* maxs = (const float*)d_in[10];
    float* out = (float*)d_out;

    const int n = in_sizes[0] / 3;

    cudaFuncSetAttribute(k_mlp, cudaFuncAttributeMaxDynamicSharedMemorySize,
                         SMEM_TOTAL);

    int blocks = (n + 255) / 256;
    k_scatter_prep<<<blocks + 513, 256>>>(x, mins, maxs, n, blocks,
                                          W0, b0, W1, W2);
    k_scan<<<1, 32>>>();
    k_mlp<<<NCTA, MLP_THREADS, SMEM_TOTAL>>>(W3, b1, b2, b3, out);
}

// round 13
// speedup vs baseline: 1.8783x; 1.8783x over previous
#include <cuda_runtime.h>
#include <cuda_fp16.h>
#include <cstdint>

#define MAX_N   (1 << 17)
#define NMODELS 8
#define H       128
#define TILE    128
#define NCTA    148
#define MLP_THREADS 256

// B row stride: 128 fp16 = 256B + 16B pad = 272B = 68 u32 (ldmatrix conflict-free)
#define BSTRIDE_U32 68
#define BUF_U32     (H * BSTRIDE_U32)      // 8704 u32 = 34816 B per image

// ---------------- scratch (device globals; no allocs allowed) ----------------
__device__ int    g_counts[NMODELS];       // atomic rank counters (self-reset in k_scan)
__device__ int    g_cnt[NMODELS];          // final per-model counts
__device__ int    g_tilebase[NMODELS + 1];
__device__ int    g_total_tiles;
__device__ int    g_perm[NMODELS * MAX_N]; // segmented
__device__ float4 g_xg[NMODELS * MAX_N];   // segmented normalized inputs
// transposed fp16 weight images B[n][k] ([layer*8+model][n][k-pairs]): hi + residual
__device__ __align__(16) uint32_t g_Bhi[16 * BUF_U32];
__device__ __align__(16) uint32_t g_Blo[16 * BUF_U32];
// packed layer0: per model, per col: (w0, w1, w2, b0)
__device__ __align__(16) float4   g_W0p[NMODELS * H];

// ---------------- helpers -----------------------------------------------------
__device__ __forceinline__ uint32_t smem_u32(const void* p) {
    uint32_t a;
    asm("{ .reg .u64 t; cvta.to.shared.u64 t, %1; cvt.u32.u64 %0, t; }"
        : "=r"(a) : "l"(p));
    return a;
}
__device__ __forceinline__ void mma16816(float* d, const uint32_t* a,
                                         uint32_t b0, uint32_t b1) {
    asm volatile(
        "mma.sync.aligned.m16n8k16.row.col.f32.f16.f16.f32 "
        "{%0,%1,%2,%3}, {%4,%5,%6,%7}, {%8,%9}, {%0,%1,%2,%3};"
        : "+f"(d[0]), "+f"(d[1]), "+f"(d[2]), "+f"(d[3])
        : "r"(a[0]), "r"(a[1]), "r"(a[2]), "r"(a[3]), "r"(b0), "r"(b1));
}
__device__ __forceinline__ void ldsm4(uint32_t* r, uint32_t addr) {
    asm volatile("ldmatrix.sync.aligned.m8n8.x4.shared.b16 {%0,%1,%2,%3}, [%4];"
                 : "=r"(r[0]), "=r"(r[1]), "=r"(r[2]), "=r"(r[3]) : "r"(addr));
}
// pack (v0 -> lower half, v1 -> upper half) as fp16x2 (single rounding)
__device__ __forceinline__ uint32_t pack_f16x2(float v0, float v1) {
    uint32_t r;
    asm("cvt.rn.f16x2.f32 %0, %1, %2;" : "=r"(r) : "f"(v1), "f"(v0));
    return r;
}
// fp16 pack + residuals (for weight hi/lo split in prep)
__device__ __forceinline__ uint32_t pack_f16_res(float v0, float v1,
                                                 float& r0, float& r1) {
    __half h0 = __float2half_rn(v0), h1 = __float2half_rn(v1);
    r0 = v0 - __half2float(h0);
    r1 = v1 - __half2float(h1);
    __half2 h = {h0, h1};
    uint32_t u;
    memcpy(&u, &h, 4);
    return u;
}

// ---------------- model index (bit-exact vs reference) ------------------------
__device__ __forceinline__ int model_index(float x0, float x1, float x2) {
    const float den = 2.0f + 1e-6f;
    int c0 = (int)((x2 + 1.0f) / den * 2.0f);
    int c1 = (int)((x1 + 1.0f) / den * 2.0f);
    int c2 = (int)((x0 + 1.0f) / den * 2.0f);
    return c0 + 2 * c1 + 4 * c2;
}

// ---------------- pass 1: fused classify+scatter (+weight prep blocks) -------
__global__ void k_scatter_prep(const float* __restrict__ x,
                               const float* __restrict__ mins,
                               const float* __restrict__ maxs, int n, int SB,
                               const float* __restrict__ W0,
                               const float* __restrict__ b0,
                               const float* __restrict__ W1,
                               const float* __restrict__ W2) {
    const int blk = blockIdx.x;
    const int tid = threadIdx.x;
    if (blk < SB) {
        __shared__ int sh_cnt[NMODELS];
        __shared__ int sh_base[NMODELS];
        if (tid < NMODELS) sh_cnt[tid] = 0;
        __syncthreads();
        int i = blk * blockDim.x + tid;
        int m = 0, rank = 0;
        float x0 = 0.f, x1 = 0.f, x2 = 0.f;
        if (i < n) {
            x0 = x[3 * i]; x1 = x[3 * i + 1]; x2 = x[3 * i + 2];
            m = model_index(x0, x1, x2);
            rank = atomicAdd(&sh_cnt[m], 1);
        }
        __syncthreads();
        if (tid < NMODELS)
            sh_base[tid] = sh_cnt[tid] ? atomicAdd(&g_counts[tid], sh_cnt[tid]) : 0;
        __syncthreads();
        if (i < n) {
            int pos = m * MAX_N + sh_base[m] + rank;
            g_perm[pos] = i;
            float mn0 = mins[3 * m], mn1 = mins[3 * m + 1], mn2 = mins[3 * m + 2];
            float mx0 = maxs[3 * m], mx1 = maxs[3 * m + 1], mx2 = maxs[3 * m + 2];
            g_xg[pos] = make_float4(-1.0f + 2.0f * (x0 - mn0) / (mx0 - mn0),
                                    -1.0f + 2.0f * (x1 - mn1) / (mx1 - mn1),
                                    -1.0f + 2.0f * (x2 - mn2) / (mx2 - mn2), 0.0f);
        }
    } else if (blk < SB + 512) {
        int t = (blk - SB) * 256 + tid;        // 0 .. 131071
        int lm = t >> 13;                      // layer*8 + model
        int w  = t & 8191;
        int nn = w >> 6;                       // output row 0..127 (R11 indexing)
        int k2 = w & 63;                       // pair of K columns
        const float* W = ((lm >> 3) ? W2 : W1) + (lm & 7) * H * H;
        int k = 2 * k2;
        float v0 = W[k * H + nn];              // B[n][k] = W[k][n]
        float v1 = W[(k + 1) * H + nn];
        float r0, r1;
        uint32_t hi = pack_f16_res(v0, v1, r0, r1);
        uint32_t lo = pack_f16x2(r0, r1);
        int off = lm * BUF_U32 + nn * BSTRIDE_U32 + k2;
        g_Bhi[off] = hi;
        g_Blo[off] = lo;
    } else {
        for (int i = tid; i < NMODELS * H; i += 256) {
            int m = i >> 7, c = i & 127;
            g_W0p[i] = make_float4(W0[m * 384 + c], W0[m * 384 + 128 + c],
                                   W0[m * 384 + 256 + c], b0[m * H + c]);
        }
    }
}

// ---------------- pass 2: tiny scan -------------------------------------------
__global__ void k_scan() {
    if (threadIdx.x == 0) {
        int t = 0;
        for (int m = 0; m < NMODELS; m++) {
            int c = g_counts[m];
            g_counts[m] = 0;          // self-reset for graph replay
            g_cnt[m] = c;
            g_tilebase[m] = t;
            t += (c + TILE - 1) / TILE;
        }
        g_tilebase[NMODELS] = t;
        g_total_tiles = t;
    }
}

// ---------------- smem layout (bytes) -----------------------------------------
#define SB_B1HI 0
#define SB_B1LO (SB_B1HI + 34816)
#define SB_B2HI (SB_B1LO + 34816)
#define SB_B2LO (SB_B2HI + 34816)
#define SB_W0P  (SB_B2LO + 34816)          // 128 * float4 = 2048
#define SB_B1   (SB_W0P + 2048)            // 512
#define SB_B2   (SB_B1 + 512)
#define SB_W3   (SB_B2 + 512)
#define SMEM_TOTAL (SB_W3 + 512)

// one GEMM layer: acc[64] += A_hi(fp16 frags) @ (B_hi + B_lo)(smem images)
// 2-term split; R11's d0/d1 interleave preserved
__device__ __forceinline__ void mma_layer(float* acc,
                                          const uint32_t* a_hi,
                                          uint32_t bhi_base, uint32_t blo_base,
                                          uint32_t lane_off) {
    #pragma unroll
    for (int kt = 0; kt < 8; kt++) {
        #pragma unroll
        for (int ntp = 0; ntp < 8; ntp++) {
            uint32_t bh[4], bl[4];
            uint32_t off = (uint32_t)(ntp * 16 * 272 + kt * 32) + lane_off;
            ldsm4(bh, bhi_base + off);
            ldsm4(bl, blo_base + off);
            float* d0 = acc + (2 * ntp) * 4;
            float* d1 = acc + (2 * ntp + 1) * 4;
            const uint32_t* ah = a_hi + kt * 4;
            mma16816(d0, ah, bh[0], bh[1]);
            mma16816(d1, ah, bh[2], bh[3]);
            mma16816(d0, ah, bl[0], bl[1]);
            mma16816(d1, ah, bl[2], bl[3]);
        }
    }
}

// ---------------- persistent fused-MLP kernel ---------------------------------
__global__ void __launch_bounds__(MLP_THREADS, 1)
k_mlp(const float* __restrict__ W3, const float* __restrict__ b1g,
      const float* __restrict__ b2g, const float* __restrict__ b3g,
      float* __restrict__ out) {
    extern __shared__ char smc[];
    const uint32_t sbase = smem_u32(smc);
    const int tid  = threadIdx.x;
    const int wid  = tid >> 5;
    const int lane = tid & 31;
    const int q2   = 2 * (lane & 3);
    const int grp  = lane >> 2;            // 0..7
    const int r0l  = wid * 16 + grp;       // local row A
    const int r1l  = r0l + 8;              // local row B

    // ldmatrix per-lane base offset within a B image
    const uint32_t lane_off =
        (uint32_t)(((lane & 7) + ((lane & 16) ? 8 : 0)) * 272 + ((lane & 8) ? 16 : 0));

    const int T = g_total_tiles;
    const int start = (int)((long long)blockIdx.x * T / NCTA);
    const int end   = (int)((long long)(blockIdx.x + 1) * T / NCTA);

    float4* W0ps = (float4*)(smc + SB_W0P);
    float*  b1s  = (float*)(smc + SB_B1);
    float*  b2s  = (float*)(smc + SB_B2);
    float*  w3s  = (float*)(smc + SB_W3);

    int cur_m = -1;
    float b3v = 0.0f;

    for (int t = start; t < end; t++) {
        int m = 0;
        while (m < NMODELS - 1 && t >= g_tilebase[m + 1]) m++;

        if (m != cur_m) {
            __syncthreads();               // prior tile's ldmatrix readers done
            const uint4* s1h = (const uint4*)(g_Bhi + (0 * 8 + m) * BUF_U32);
            const uint4* s1l = (const uint4*)(g_Blo + (0 * 8 + m) * BUF_U32);
            const uint4* s2h = (const uint4*)(g_Bhi + (1 * 8 + m) * BUF_U32);
            const uint4* s2l = (const uint4*)(g_Blo + (1 * 8 + m) * BUF_U32);
            uint4* d1h = (uint4*)(smc + SB_B1HI);
            uint4* d1l = (uint4*)(smc + SB_B1LO);
            uint4* d2h = (uint4*)(smc + SB_B2HI);
            uint4* d2l = (uint4*)(smc + SB_B2LO);
            for (int i = tid; i < 2176; i += MLP_THREADS) {
                d1h[i] = s1h[i];
                d1l[i] = s1l[i];
                d2h[i] = s2h[i];
                d2l[i] = s2l[i];
            }
            if (tid < H) {
                W0ps[tid] = g_W0p[m * H + tid];
                b1s[tid]  = b1g[m * H + tid];
                b2s[tid]  = b2g[m * H + tid];
                w3s[tid]  = W3[m * H + tid];
            }
            b3v = b3g[m];
            cur_m = m;
            __syncthreads();
        }

        const int row0 = (t - g_tilebase[m]) * TILE;      // within segment
        const int rows = min(TILE, g_cnt[m] - row0);
        const int seg  = m * MAX_N + row0;

        // ---- layer 0: compute A-fragments directly in registers (fp16) ------
        float4 xa = (r0l < rows) ? g_xg[seg + r0l] : make_float4(0.f, 0.f, 0.f, 0.f);
        float4 xb = (r1l < rows) ? g_xg[seg + r1l] : make_float4(0.f, 0.f, 0.f, 0.f);

        uint32_t a_hi[32];
        #pragma unroll
        for (int kt = 0; kt < 8; kt++) {
            int c0 = kt * 16 + q2;
            float4 wA0 = W0ps[c0], wA1 = W0ps[c0 + 1];
            float4 wB0 = W0ps[c0 + 8], wB1 = W0ps[c0 + 9];
            float va0 = fmaxf(fmaf(xa.x, wA0.x, fmaf(xa.y, wA0.y, fmaf(xa.z, wA0.z, wA0.w))), 0.f);
            float va1 = fmaxf(fmaf(xa.x, wA1.x, fmaf(xa.y, wA1.y, fmaf(xa.z, wA1.z, wA1.w))), 0.f);
            float vb0 = fmaxf(fmaf(xb.x, wA0.x, fmaf(xb.y, wA0.y, fmaf(xb.z, wA0.z, wA0.w))), 0.f);
            float vb1 = fmaxf(fmaf(xb.x, wA1.x, fmaf(xb.y, wA1.y, fmaf(xb.z, wA1.z, wA1.w))), 0.f);
            float va2 = fmaxf(fmaf(xa.x, wB0.x, fmaf(xa.y, wB0.y, fmaf(xa.z, wB0.z, wB0.w))), 0.f);
            float va3 = fmaxf(fmaf(xa.x, wB1.x, fmaf(xa.y, wB1.y, fmaf(xa.z, wB1.z, wB1.w))), 0.f);
            float vb2 = fmaxf(fmaf(xb.x, wB0.x, fmaf(xb.y, wB0.y, fmaf(xb.z, wB0.z, wB0.w))), 0.f);
            float vb3 = fmaxf(fmaf(xb.x, wB1.x, fmaf(xb.y, wB1.y, fmaf(xb.z, wB1.z, wB1.w))), 0.f);
            a_hi[kt * 4 + 0] = pack_f16x2(va0, va1);
            a_hi[kt * 4 + 1] = pack_f16x2(vb0, vb1);
            a_hi[kt * 4 + 2] = pack_f16x2(va2, va3);
            a_hi[kt * 4 + 3] = pack_f16x2(vb2, vb3);
        }

        // ---- layer 1 ---------------------------------------------------------
        float acc[64];
        #pragma unroll
        for (int i = 0; i < 64; i++) acc[i] = 0.0f;
        mma_layer(acc, a_hi, sbase + SB_B1HI, sbase + SB_B1LO, lane_off);

        // epilogue: bias + relu -> new A-fragments (C frag layout == A frag layout)
        #pragma unroll
        for (int kt = 0; kt < 8; kt++) {
            int ntA = 2 * kt, ntB = 2 * kt + 1;
            int cbA = ntA * 8 + q2, cbB = ntB * 8 + q2;
            float bA0 = b1s[cbA], bA1 = b1s[cbA + 1];
            float bB0 = b1s[cbB], bB1 = b1s[cbB + 1];
            float va0 = fmaxf(acc[ntA * 4 + 0] + bA0, 0.f);
            float va1 = fmaxf(acc[ntA * 4 + 1] + bA1, 0.f);
            float vb0 = fmaxf(acc[ntA * 4 + 2] + bA0, 0.f);
            float vb1 = fmaxf(acc[ntA * 4 + 3] + bA1, 0.f);
            float va2 = fmaxf(acc[ntB * 4 + 0] + bB0, 0.f);
            float va3 = fmaxf(acc[ntB * 4 + 1] + bB1, 0.f);
            float vb2 = fmaxf(acc[ntB * 4 + 2] + bB0, 0.f);
            float vb3 = fmaxf(acc[ntB * 4 + 3] + bB1, 0.f);
            a_hi[kt * 4 + 0] = pack_f16x2(va0, va1);
            a_hi[kt * 4 + 1] = pack_f16x2(vb0, vb1);
            a_hi[kt * 4 + 2] = pack_f16x2(va2, va3);
            a_hi[kt * 4 + 3] = pack_f16x2(vb2, vb3);
        }

        // ---- layer 2 ---------------------------------------------------------
        #pragma unroll
        for (int i = 0; i < 64; i++) acc[i] = 0.0f;
        mma_layer(acc, a_hi, sbase + SB_B2HI, sbase + SB_B2LO, lane_off);

        // ---- layer 3: relu + dot(w3) + cross-lane reduce ---------------------
        float s0 = 0.f, s1 = 0.f;
        #pragma unroll
        for (int nt = 0; nt < 16; nt++) {
            int cb = nt * 8 + q2;
            float w3a = w3s[cb], w3b = w3s[cb + 1];
            float b2a = b2s[cb], b2b = b2s[cb + 1];
            s0 = fmaf(fmaxf(acc[nt * 4 + 0] + b2a, 0.f), w3a, s0);
            s0 = fmaf(fmaxf(acc[nt * 4 + 1] + b2b, 0.f), w3b, s0);
            s1 = fmaf(fmaxf(acc[nt * 4 + 2] + b2a, 0.f), w3a, s1);
            s1 = fmaf(fmaxf(acc[nt * 4 + 3] + b2b, 0.f), w3b, s1);
        }
        s0 += __shfl_xor_sync(0xffffffffu, s0, 1);
        s0 += __shfl_xor_sync(0xffffffffu, s0, 2);
        s1 += __shfl_xor_sync(0xffffffffu, s1, 1);
        s1 += __shfl_xor_sync(0xffffffffu, s1, 2);
        if ((lane & 3) == 0) {
            if (r0l < rows) out[g_perm[seg + r0l]] = s0 + b3v;
            if (r1l < rows) out[g_perm[seg + r1l]] = s1 + b3v;
        }
    }
}

// ---------------- launch -------------------------------------------------------
extern "C" void kernel_launch(void* const* d_in, const int* in_sizes, int n_in,
                              void* d_out, int out_size) {
    const float* x    = (const float*)d_in[0];
    const float* W0   = (const float*)d_in[1];
    const float* b0   = (const float*)d_in[2];
    const float* W1   = (const float*)d_in[3];
    const float* b1   = (const float*)d_in[4];
    const float* W2   = (const float*)d_in[5];
    const float* b2   = (const float*)d_in[6];
    const float* W3   = (const float*)d_in[7];
    const float* b3   = (const float*)d_in[8];
    const float* mins = (const float*)d_in[9];
    const float* maxs = (const float*)d_in[10];
    float* out = (float*)d_out;

    const int n = in_sizes[0] / 3;

    cudaFuncSetAttribute(k_mlp, cudaFuncAttributeMaxDynamicSharedMemorySize,
                         SMEM_TOTAL);

    int blocks = (n + 255) / 256;
    k_scatter_prep<<<blocks + 513, 256>>>(x, mins, maxs, n, blocks,
                                          W0, b0, W1, W2);
    k_scan<<<1, 32>>>();
    k_mlp<<<NCTA, MLP_THREADS, SMEM_TOTAL>>>(W3, b1, b2, b3, out);
}